// round 1
// baseline (speedup 1.0000x reference)
#include <cuda_runtime.h>

#define USER_NUM 100000
#define ITEM_NUM 50000
#define NTOT     (USER_NUM + ITEM_NUM)     // 150000
#define EMB      64
#define NNZ      3000000
#define EPS      0.1f
#define NELEM    (NTOT * EMB)              // 9,600,000

// Scratch (no allocation allowed in kernel_launch): three [N, 64] fp32 buffers.
__device__ float g_ego[NELEM];   // current layer input embedding
__device__ float g_nxt[NELEM];   // SpMM accumulation target (must be zero before each SpMM)
__device__ float g_acc[NELEM];   // running sum of layer outputs

// ---------------------------------------------------------------------------
// init: g_ego = concat(user_emb, item_emb); g_nxt = 0   (vectorized float4)
// ---------------------------------------------------------------------------
__global__ void init_kernel(const float* __restrict__ ue, const float* __restrict__ ie) {
    int idx = blockIdx.x * blockDim.x + threadIdx.x;       // float4 index
    if (idx >= NELEM / 4) return;
    float4 v;
    if (idx < USER_NUM * EMB / 4) v = ((const float4*)ue)[idx];
    else                          v = ((const float4*)ie)[idx - USER_NUM * EMB / 4];
    ((float4*)g_ego)[idx] = v;
    ((float4*)g_nxt)[idx] = make_float4(0.f, 0.f, 0.f, 0.f);
}

// ---------------------------------------------------------------------------
// SpMM: g_nxt[rows[i]] += vals[i] * g_ego[cols[i]]   (COO, scatter via red.v4)
// 16 lanes cooperate on one nnz; each lane owns one float4 (16B) of the 64-wide row.
// ---------------------------------------------------------------------------
__global__ void __launch_bounds__(256) spmm_kernel(const float* __restrict__ vals,
                                                   const int* __restrict__ rows,
                                                   const int* __restrict__ cols) {
    long long t = (long long)blockIdx.x * blockDim.x + threadIdx.x;
    int i = (int)(t >> 4);          // nnz index
    int l = (int)(t & 15);          // lane-of-16 (float4 slice)
    if (i >= NNZ) return;

    float v = vals[i];
    int   c = cols[i];
    int   r = rows[i];

    float4 x4 = ((const float4*)(g_ego + (long long)c * EMB))[l];
    float4 p  = make_float4(v * x4.x, v * x4.y, v * x4.z, v * x4.w);

    float* dst = g_nxt + (long long)r * EMB + l * 4;
    asm volatile("red.global.add.v4.f32 [%0], {%1, %2, %3, %4};"
                 :: "l"(dst), "f"(p.x), "f"(p.y), "f"(p.z), "f"(p.w)
                 : "memory");
}

// ---------------------------------------------------------------------------
// perturb + accumulate (+ finalize):
//   e   = g_nxt + sign(g_nxt) * (noise_k / max(||noise_k||_row, 1e-12)) * EPS
//   acc = (FIRST ? g_ego : g_acc) + e
//   g_ego = e ; if LAST: out = acc * 0.25 ; else: g_acc = acc, g_nxt = 0
// One warp per row (64 elems = float2 per lane); shfl reduce for the row norm.
// ---------------------------------------------------------------------------
template <bool FIRST, bool LAST>
__global__ void __launch_bounds__(256) perturb_kernel(const float* __restrict__ noise_k,
                                                      float* __restrict__ out) {
    int warp = (blockIdx.x * blockDim.x + threadIdx.x) >> 5;
    int lane = threadIdx.x & 31;
    if (warp >= NTOT) return;

    long long base = (long long)warp * EMB + 2 * lane;

    float2 n = *(const float2*)(noise_k + base);
    float ss = n.x * n.x + n.y * n.y;
    #pragma unroll
    for (int o = 16; o; o >>= 1) ss += __shfl_xor_sync(0xffffffffu, ss, o);
    float inv = EPS / fmaxf(sqrtf(ss), 1e-12f);

    float2 v = *(const float2*)(g_nxt + base);
    float s0 = (v.x > 0.f) ? 1.f : ((v.x < 0.f) ? -1.f : 0.f);
    float s1 = (v.y > 0.f) ? 1.f : ((v.y < 0.f) ? -1.f : 0.f);
    float e0 = v.x + s0 * n.x * inv;
    float e1 = v.y + s1 * n.y * inv;

    float2 prev = FIRST ? *(const float2*)(g_ego + base)
                        : *(const float2*)(g_acc + base);
    float a0 = prev.x + e0;
    float a1 = prev.y + e1;

    *(float2*)(g_ego + base) = make_float2(e0, e1);
    if (LAST) {
        *(float2*)(out + base) = make_float2(a0 * 0.25f, a1 * 0.25f);
    } else {
        *(float2*)(g_acc + base) = make_float2(a0, a1);
        *(float2*)(g_nxt + base) = make_float2(0.f, 0.f);   // re-zero for next layer
    }
}

// ---------------------------------------------------------------------------
// launch: init, 3 x (spmm, perturb). All on default stream; graph-capturable.
// Inputs (metadata order): 0 user_emb, 1 item_emb, 2 adj_vals, 3 noise,
//                          4 adj_rows, 5 adj_cols
// ---------------------------------------------------------------------------
extern "C" void kernel_launch(void* const* d_in, const int* in_sizes, int n_in,
                              void* d_out, int out_size) {
    const float* ue    = (const float*)d_in[0];
    const float* ie    = (const float*)d_in[1];
    const float* vals  = (const float*)d_in[2];
    const float* noise = (const float*)d_in[3];
    const int*   rows  = (const int*)d_in[4];
    const int*   cols  = (const int*)d_in[5];
    float* out = (float*)d_out;

    (void)in_sizes; (void)n_in; (void)out_size;

    const int ew_blocks    = (NELEM / 4 + 255) / 256;               // init (float4)
    const int spmm_threads = NNZ * 16;                              // 16 lanes / nnz
    const int spmm_blocks  = (spmm_threads + 255) / 256;
    const int pert_blocks  = (NTOT * 32 + 255) / 256;               // warp / row

    init_kernel<<<ew_blocks, 256>>>(ue, ie);

    // layer 0
    spmm_kernel<<<spmm_blocks, 256>>>(vals, rows, cols);
    perturb_kernel<true, false><<<pert_blocks, 256>>>(noise + 0LL * NELEM, out);
    // layer 1
    spmm_kernel<<<spmm_blocks, 256>>>(vals, rows, cols);
    perturb_kernel<false, false><<<pert_blocks, 256>>>(noise + 1LL * NELEM, out);
    // layer 2
    spmm_kernel<<<spmm_blocks, 256>>>(vals, rows, cols);
    perturb_kernel<false, true><<<pert_blocks, 256>>>(noise + 2LL * NELEM, out);
}

// round 3
// speedup vs baseline: 2.0371x; 2.0371x over previous
#include <cuda_runtime.h>

#define USER_NUM 100000
#define ITEM_NUM 50000
#define NTOT     (USER_NUM + ITEM_NUM)     // 150000
#define EMB      64
#define NNZ      3000000
#define EPS      0.1f
#define NELEM    (NTOT * EMB)              // 9,600,000
#define NBLK     ((NTOT + 1023) / 1024)    // 147 scan blocks

// ---- static scratch (no allocs allowed; referenced ONLY in device code) ----
__device__ float  g_egoA[NELEM];
__device__ float  g_egoB[NELEM];
__device__ float  g_acc[NELEM];
__device__ int    g_cnt[NTOT];
__device__ int    g_row_ptr[NTOT + 1];
__device__ int    g_cursor[NTOT];
__device__ int    g_blocksum[NBLK];
__device__ int    g_blockoff[NBLK];
__device__ float2 g_pair[NNZ];             // {val, __int_as_float(col)} grouped by row

// ---------------------------------------------------------------------------
// init: egoA = concat(user,item); acc = same; zero row histogram
// ---------------------------------------------------------------------------
__global__ void init_kernel(const float* __restrict__ ue, const float* __restrict__ ie) {
    int idx = blockIdx.x * blockDim.x + threadIdx.x;       // float4 index
    if (idx < NTOT) g_cnt[idx] = 0;
    if (idx >= NELEM / 4) return;
    float4 v;
    if (idx < USER_NUM * EMB / 4) v = ((const float4*)ue)[idx];
    else                          v = ((const float4*)ie)[idx - USER_NUM * EMB / 4];
    ((float4*)g_egoA)[idx] = v;
    ((float4*)g_acc)[idx]  = v;
}

// ---------------------------------------------------------------------------
// CSR build: histogram -> 3-step exclusive scan -> scatter (val,col) pairs
// ---------------------------------------------------------------------------
__global__ void hist_kernel(const int* __restrict__ rows) {
    int i = blockIdx.x * blockDim.x + threadIdx.x;
    if (i < NNZ) atomicAdd(&g_cnt[rows[i]], 1);
}

__global__ void scan1_kernel() {                 // per-block exclusive scan
    __shared__ int sh[1024];
    int i = blockIdx.x * 1024 + threadIdx.x;
    int v = (i < NTOT) ? g_cnt[i] : 0;
    sh[threadIdx.x] = v;
    __syncthreads();
    #pragma unroll
    for (int o = 1; o < 1024; o <<= 1) {
        int t = (threadIdx.x >= o) ? sh[threadIdx.x - o] : 0;
        __syncthreads();
        sh[threadIdx.x] += t;
        __syncthreads();
    }
    if (i < NTOT) g_row_ptr[i] = sh[threadIdx.x] - v;      // exclusive
    if (threadIdx.x == 1023) g_blocksum[blockIdx.x] = sh[1023];
}

__global__ void scan2_kernel() {                 // scan of 147 block sums
    __shared__ int sh[NBLK];
    int t = threadIdx.x;
    if (t < NBLK) sh[t] = g_blocksum[t];
    __syncthreads();
    if (t == 0) {
        int run = 0;
        for (int b = 0; b < NBLK; b++) { int c = sh[b]; sh[b] = run; run += c; }
        g_row_ptr[NTOT] = run;                   // == NNZ
    }
    __syncthreads();
    if (t < NBLK) g_blockoff[t] = sh[t];
}

__global__ void scan3_kernel() {                 // add block offsets; init cursors
    int i = blockIdx.x * blockDim.x + threadIdx.x;
    if (i >= NTOT) return;
    int v = g_row_ptr[i] + g_blockoff[i >> 10];
    g_row_ptr[i] = v;
    g_cursor[i]  = v;
}

__global__ void scatter_kernel(const float* __restrict__ vals,
                               const int* __restrict__ rows,
                               const int* __restrict__ cols) {
    int i = blockIdx.x * blockDim.x + threadIdx.x;
    if (i >= NNZ) return;
    int r = rows[i];
    int pos = atomicAdd(&g_cursor[r], 1);
    g_pair[pos] = make_float2(vals[i], __int_as_float(cols[i]));
}

// ---------------------------------------------------------------------------
// Fused layer: gather-SpMM (CSR, half-warp per row, register accumulate)
//              + sign(.)*normalize(noise)*EPS perturb + acc update (+finalize)
// Ping-pong buffers selected by template param (device symbols used in
// DEVICE code only — host cannot take their address).
// ---------------------------------------------------------------------------
__device__ __forceinline__ float sgn(float x) {
    return (x > 0.f) ? 1.f : ((x < 0.f) ? -1.f : 0.f);
}

template <int PP, bool LAST>
__global__ void __launch_bounds__(256) layer_kernel(const float* __restrict__ noise_k,
                                                    float* __restrict__ out) {
    const float* __restrict__ egoIn  = (PP == 0) ? g_egoA : g_egoB;
    float*       __restrict__ egoOut = (PP == 0) ? g_egoB : g_egoA;

    int hw = (blockIdx.x * blockDim.x + threadIdx.x) >> 4;  // half-warp = row
    int l  = threadIdx.x & 15;                              // float4 slice
    if (hw >= NTOT) return;

    int beg = g_row_ptr[hw];
    int end = g_row_ptr[hw + 1];

    const float4* ego4 = (const float4*)egoIn;
    float4 a = make_float4(0.f, 0.f, 0.f, 0.f);

    int j = beg;
    for (; j + 4 <= end; j += 4) {                          // unroll-4 for MLP
        float2 p0 = g_pair[j],     p1 = g_pair[j + 1];
        float2 p2 = g_pair[j + 2], p3 = g_pair[j + 3];
        float4 x0 = ego4[__float_as_int(p0.y) * 16 + l];
        float4 x1 = ego4[__float_as_int(p1.y) * 16 + l];
        float4 x2 = ego4[__float_as_int(p2.y) * 16 + l];
        float4 x3 = ego4[__float_as_int(p3.y) * 16 + l];
        a.x += p0.x * x0.x; a.y += p0.x * x0.y; a.z += p0.x * x0.z; a.w += p0.x * x0.w;
        a.x += p1.x * x1.x; a.y += p1.x * x1.y; a.z += p1.x * x1.z; a.w += p1.x * x1.w;
        a.x += p2.x * x2.x; a.y += p2.x * x2.y; a.z += p2.x * x2.z; a.w += p2.x * x2.w;
        a.x += p3.x * x3.x; a.y += p3.x * x3.y; a.z += p3.x * x3.z; a.w += p3.x * x3.w;
    }
    for (; j < end; ++j) {
        float2 p = g_pair[j];
        float4 x = ego4[__float_as_int(p.y) * 16 + l];
        a.x += p.x * x.x; a.y += p.x * x.y; a.z += p.x * x.z; a.w += p.x * x.w;
    }

    // noise row-norm over 64 elems (16 lanes x 4), shfl reduce within half-warp
    float4 n = ((const float4*)noise_k)[hw * 16 + l];
    float ss = n.x * n.x + n.y * n.y + n.z * n.z + n.w * n.w;
    ss += __shfl_xor_sync(0xffffffffu, ss, 8, 16);
    ss += __shfl_xor_sync(0xffffffffu, ss, 4, 16);
    ss += __shfl_xor_sync(0xffffffffu, ss, 2, 16);
    ss += __shfl_xor_sync(0xffffffffu, ss, 1, 16);
    float inv = EPS / fmaxf(sqrtf(ss), 1e-12f);

    float4 e;
    e.x = a.x + sgn(a.x) * n.x * inv;
    e.y = a.y + sgn(a.y) * n.y * inv;
    e.z = a.z + sgn(a.z) * n.z * inv;
    e.w = a.w + sgn(a.w) * n.w * inv;

    long long o = (long long)hw * 16 + l;
    ((float4*)egoOut)[o] = e;

    float4 pa = ((const float4*)g_acc)[o];
    pa.x += e.x; pa.y += e.y; pa.z += e.z; pa.w += e.w;
    if (LAST) {
        ((float4*)out)[o] = make_float4(pa.x * 0.25f, pa.y * 0.25f, pa.z * 0.25f, pa.w * 0.25f);
    } else {
        ((float4*)g_acc)[o] = pa;
    }
}

// ---------------------------------------------------------------------------
// launch
// Inputs: 0 user_emb, 1 item_emb, 2 adj_vals, 3 noise, 4 adj_rows, 5 adj_cols
// ---------------------------------------------------------------------------
extern "C" void kernel_launch(void* const* d_in, const int* in_sizes, int n_in,
                              void* d_out, int out_size) {
    const float* ue    = (const float*)d_in[0];
    const float* ie    = (const float*)d_in[1];
    const float* vals  = (const float*)d_in[2];
    const float* noise = (const float*)d_in[3];
    const int*   rows  = (const int*)d_in[4];
    const int*   cols  = (const int*)d_in[5];
    float* out = (float*)d_out;
    (void)in_sizes; (void)n_in; (void)out_size;

    const int ew_blocks   = (NELEM / 4 + 255) / 256;
    const int nnz_blocks  = (NNZ + 255) / 256;
    const int row_blocks  = (NTOT + 255) / 256;
    const int lay_blocks  = (NTOT * 16 + 255) / 256;        // half-warp per row

    init_kernel<<<ew_blocks, 256>>>(ue, ie);

    // CSR build (reused by all 3 layers)
    hist_kernel<<<nnz_blocks, 256>>>(rows);
    scan1_kernel<<<NBLK, 1024>>>();
    scan2_kernel<<<1, 256>>>();
    scan3_kernel<<<row_blocks, 256>>>();
    scatter_kernel<<<nnz_blocks, 256>>>(vals, rows, cols);

    // 3 fused layers (ego ping-pong: A->B, B->A, A->B)
    layer_kernel<0, false><<<lay_blocks, 256>>>(noise + 0LL * NELEM, out);
    layer_kernel<1, false><<<lay_blocks, 256>>>(noise + 1LL * NELEM, out);
    layer_kernel<0, true ><<<lay_blocks, 256>>>(noise + 2LL * NELEM, out);
}

// round 4
// speedup vs baseline: 2.2614x; 1.1101x over previous
#include <cuda_runtime.h>

#define USER_NUM 100000
#define ITEM_NUM 50000
#define NTOT     (USER_NUM + ITEM_NUM)     // 150000
#define EMB      64
#define NNZ      3000000
#define EPS      0.1f
#define NELEM    (NTOT * EMB)              // 9,600,000
#define NBLK     ((NTOT + 1023) / 1024)    // 147 scan blocks

// ---- static scratch (referenced ONLY in device code) -----------------------
__device__ float  g_egoA[NELEM];           // ego0 (kept until the end)
__device__ float  g_egoB[NELEM];           // e1
__device__ float  g_egoC[NELEM];           // e2
__device__ int    g_cnt[NTOT];
__device__ int    g_row_ptr[NTOT + 1];
__device__ int    g_cursor[NTOT];
__device__ int    g_blocksum[NBLK];
__device__ float2 g_pair[NNZ];             // {val, __int_as_float(col)} grouped by row

// ---------------------------------------------------------------------------
// init: egoA = concat(user,item); zero histogram; row_ptr[NTOT] = NNZ
// ---------------------------------------------------------------------------
__global__ void init_kernel(const float* __restrict__ ue, const float* __restrict__ ie) {
    int idx = blockIdx.x * blockDim.x + threadIdx.x;       // float4 index
    if (idx < NTOT) g_cnt[idx] = 0;
    if (idx == 0)   g_row_ptr[NTOT] = NNZ;
    if (idx >= NELEM / 4) return;
    float4 v;
    if (idx < USER_NUM * EMB / 4) v = ((const float4*)ue)[idx];
    else                          v = ((const float4*)ie)[idx - USER_NUM * EMB / 4];
    ((float4*)g_egoA)[idx] = v;
}

// ---------------------------------------------------------------------------
// CSR build: histogram -> per-block scan -> (blockoff reduce + apply) -> scatter
// ---------------------------------------------------------------------------
__global__ void hist_kernel(const int* __restrict__ rows) {
    int i = blockIdx.x * blockDim.x + threadIdx.x;
    if (i < NNZ) atomicAdd(&g_cnt[rows[i]], 1);
}

__global__ void scan1_kernel() {                 // per-1024-block exclusive scan
    __shared__ int sh[1024];
    int i = blockIdx.x * 1024 + threadIdx.x;
    int v = (i < NTOT) ? g_cnt[i] : 0;
    sh[threadIdx.x] = v;
    __syncthreads();
    #pragma unroll
    for (int o = 1; o < 1024; o <<= 1) {
        int t = (threadIdx.x >= o) ? sh[threadIdx.x - o] : 0;
        __syncthreads();
        sh[threadIdx.x] += t;
        __syncthreads();
    }
    if (i < NTOT) g_row_ptr[i] = sh[threadIdx.x] - v;      // exclusive within block
    if (threadIdx.x == 1023) g_blocksum[blockIdx.x] = sh[1023];
}

// merged scan2+scan3: each 256-row block shares one scan1-block id; compute the
// prefix of blocksums with a shared tree-reduce, then apply + init cursors.
__global__ void scan23_kernel() {
    __shared__ int sh[256];
    int i    = blockIdx.x * 256 + threadIdx.x;
    int sblk = (blockIdx.x * 256) >> 10;                   // same for whole block
    int t    = threadIdx.x;
    sh[t] = (t < NBLK && t < sblk) ? g_blocksum[t] : 0;    // mask: strictly before
    __syncthreads();
    #pragma unroll
    for (int o = 128; o; o >>= 1) {
        if (t < o) sh[t] += sh[t + o];
        __syncthreads();
    }
    int off = sh[0];
    if (i >= NTOT) return;
    int v = g_row_ptr[i] + off;
    g_row_ptr[i] = v;
    g_cursor[i]  = v;
}

__global__ void scatter_kernel(const float* __restrict__ vals,
                               const int* __restrict__ rows,
                               const int* __restrict__ cols) {
    int i = blockIdx.x * blockDim.x + threadIdx.x;
    if (i >= NNZ) return;
    int r = rows[i];
    int pos = atomicAdd(&g_cursor[r], 1);
    g_pair[pos] = make_float2(vals[i], __int_as_float(cols[i]));
}

// ---------------------------------------------------------------------------
// Fused layer: gather-SpMM (CSR, half-warp per row, register accumulate)
//              + sign-noise perturb; LAST layer also averages A,B,C,e3 -> out.
// Buffers selected by template param (device symbols used in device code only).
// ---------------------------------------------------------------------------
__device__ __forceinline__ float sgn(float x) {
    return (x > 0.f) ? 1.f : ((x < 0.f) ? -1.f : 0.f);
}

// L = 0: A -> B.  L = 1: B -> C.  L = 2: in C, write averaged out.
template <int L>
__global__ void __launch_bounds__(256) layer_kernel(const float* __restrict__ noise_k,
                                                    float* __restrict__ out) {
    const float* __restrict__ egoIn = (L == 0) ? g_egoA : ((L == 1) ? g_egoB : g_egoC);

    int hw = (blockIdx.x * blockDim.x + threadIdx.x) >> 4;  // half-warp = row
    int l  = threadIdx.x & 15;                              // float4 slice
    if (hw >= NTOT) return;

    int beg = g_row_ptr[hw];
    int end = g_row_ptr[hw + 1];

    const float4* ego4 = (const float4*)egoIn;
    float4 a = make_float4(0.f, 0.f, 0.f, 0.f);

    int j = beg;
    for (; j + 4 <= end; j += 4) {                          // unroll-4 for MLP
        float2 p0 = g_pair[j],     p1 = g_pair[j + 1];
        float2 p2 = g_pair[j + 2], p3 = g_pair[j + 3];
        float4 x0 = ego4[__float_as_int(p0.y) * 16 + l];
        float4 x1 = ego4[__float_as_int(p1.y) * 16 + l];
        float4 x2 = ego4[__float_as_int(p2.y) * 16 + l];
        float4 x3 = ego4[__float_as_int(p3.y) * 16 + l];
        a.x += p0.x * x0.x; a.y += p0.x * x0.y; a.z += p0.x * x0.z; a.w += p0.x * x0.w;
        a.x += p1.x * x1.x; a.y += p1.x * x1.y; a.z += p1.x * x1.z; a.w += p1.x * x1.w;
        a.x += p2.x * x2.x; a.y += p2.x * x2.y; a.z += p2.x * x2.z; a.w += p2.x * x2.w;
        a.x += p3.x * x3.x; a.y += p3.x * x3.y; a.z += p3.x * x3.z; a.w += p3.x * x3.w;
    }
    for (; j < end; ++j) {
        float2 p = g_pair[j];
        float4 x = ego4[__float_as_int(p.y) * 16 + l];
        a.x += p.x * x.x; a.y += p.x * x.y; a.z += p.x * x.z; a.w += p.x * x.w;
    }

    // noise row-norm over 64 elems (16 lanes x 4), shfl reduce within half-warp
    float4 n = ((const float4*)noise_k)[hw * 16 + l];
    float ss = n.x * n.x + n.y * n.y + n.z * n.z + n.w * n.w;
    ss += __shfl_xor_sync(0xffffffffu, ss, 8, 16);
    ss += __shfl_xor_sync(0xffffffffu, ss, 4, 16);
    ss += __shfl_xor_sync(0xffffffffu, ss, 2, 16);
    ss += __shfl_xor_sync(0xffffffffu, ss, 1, 16);
    float inv = EPS / fmaxf(sqrtf(ss), 1e-12f);

    float4 e;
    e.x = a.x + sgn(a.x) * n.x * inv;
    e.y = a.y + sgn(a.y) * n.y * inv;
    e.z = a.z + sgn(a.z) * n.z * inv;
    e.w = a.w + sgn(a.w) * n.w * inv;

    long long o = (long long)hw * 16 + l;
    if (L == 0) {
        ((float4*)g_egoB)[o] = e;
    } else if (L == 1) {
        ((float4*)g_egoC)[o] = e;
    } else {
        float4 z0 = ((const float4*)g_egoA)[o];     // ego0
        float4 z1 = ((const float4*)g_egoB)[o];     // e1
        float4 z2 = ((const float4*)g_egoC)[o];     // e2
        ((float4*)out)[o] = make_float4((z0.x + z1.x + z2.x + e.x) * 0.25f,
                                        (z0.y + z1.y + z2.y + e.y) * 0.25f,
                                        (z0.z + z1.z + z2.z + e.z) * 0.25f,
                                        (z0.w + z1.w + z2.w + e.w) * 0.25f);
    }
}

// ---------------------------------------------------------------------------
// launch
// Inputs: 0 user_emb, 1 item_emb, 2 adj_vals, 3 noise, 4 adj_rows, 5 adj_cols
// ---------------------------------------------------------------------------
extern "C" void kernel_launch(void* const* d_in, const int* in_sizes, int n_in,
                              void* d_out, int out_size) {
    const float* ue    = (const float*)d_in[0];
    const float* ie    = (const float*)d_in[1];
    const float* vals  = (const float*)d_in[2];
    const float* noise = (const float*)d_in[3];
    const int*   rows  = (const int*)d_in[4];
    const int*   cols  = (const int*)d_in[5];
    float* out = (float*)d_out;
    (void)in_sizes; (void)n_in; (void)out_size;

    const int ew_blocks   = (NELEM / 4 + 255) / 256;
    const int nnz_blocks  = (NNZ + 255) / 256;
    const int row_blocks  = (NTOT + 255) / 256;
    const int lay_blocks  = (NTOT * 16 + 255) / 256;        // half-warp per row

    init_kernel<<<ew_blocks, 256>>>(ue, ie);

    // CSR build (reused by all 3 layers)
    hist_kernel<<<nnz_blocks, 256>>>(rows);
    scan1_kernel<<<NBLK, 1024>>>();
    scan23_kernel<<<row_blocks, 256>>>();
    scatter_kernel<<<nnz_blocks, 256>>>(vals, rows, cols);

    // 3 fused layers: A->B, B->C, C->(averaged out)
    layer_kernel<0><<<lay_blocks, 256>>>(noise + 0LL * NELEM, out);
    layer_kernel<1><<<lay_blocks, 256>>>(noise + 1LL * NELEM, out);
    layer_kernel<2><<<lay_blocks, 256>>>(noise + 2LL * NELEM, out);
}

// round 5
// speedup vs baseline: 2.8365x; 1.2543x over previous
#include <cuda_runtime.h>
#include <cuda_fp16.h>

#define USER_NUM 100000
#define ITEM_NUM 50000
#define NTOT     (USER_NUM + ITEM_NUM)     // 150000
#define EMB      64
#define NNZ      3000000
#define EPS      0.1f
#define NELEM    (NTOT * EMB)              // 9,600,000
#define NBLK     ((NTOT + 1023) / 1024)    // 147 scan blocks

// ---- static scratch (referenced ONLY in device code) -----------------------
__device__ __half g_halfA[NELEM];          // fp16 ego0 (gather source, layer 0)
__device__ __half g_halfB[NELEM];          // fp16 e1
__device__ __half g_halfC[NELEM];          // fp16 e2
__device__ int    g_cnt[NTOT];
__device__ int    g_row_ptr[NTOT + 1];
__device__ int    g_cursor[NTOT];
__device__ int    g_blocksum[NBLK];
__device__ float2 g_pair[NNZ];             // {val, __int_as_float(col)} grouped by row

// ---- fp16 <-> fp32 helpers (8B vector ops) ---------------------------------
__device__ __forceinline__ float4 ldh4(const __half* p) {
    uint2 u = *(const uint2*)p;
    __half2 h0 = *reinterpret_cast<__half2*>(&u.x);
    __half2 h1 = *reinterpret_cast<__half2*>(&u.y);
    float2 f0 = __half22float2(h0);
    float2 f1 = __half22float2(h1);
    return make_float4(f0.x, f0.y, f1.x, f1.y);
}
__device__ __forceinline__ void sth4(__half* p, float4 v) {
    __half2 h0 = __floats2half2_rn(v.x, v.y);
    __half2 h1 = __floats2half2_rn(v.z, v.w);
    uint2 u;
    u.x = *reinterpret_cast<unsigned*>(&h0);
    u.y = *reinterpret_cast<unsigned*>(&h1);
    *(uint2*)p = u;
}

// ---------------------------------------------------------------------------
// init: halfA = fp16(concat(user,item)); zero histogram; row_ptr[NTOT] = NNZ
// ---------------------------------------------------------------------------
__global__ void init_kernel(const float* __restrict__ ue, const float* __restrict__ ie) {
    int idx = blockIdx.x * blockDim.x + threadIdx.x;       // float4 index
    if (idx < NTOT) g_cnt[idx] = 0;
    if (idx == 0)   g_row_ptr[NTOT] = NNZ;
    if (idx >= NELEM / 4) return;
    float4 v;
    if (idx < USER_NUM * EMB / 4) v = ((const float4*)ue)[idx];
    else                          v = ((const float4*)ie)[idx - USER_NUM * EMB / 4];
    sth4(g_halfA + (long long)idx * 4, v);
}

// ---------------------------------------------------------------------------
// CSR build: histogram -> per-block scan -> blockoff reduce+apply -> scatter
// ---------------------------------------------------------------------------
__global__ void hist_kernel(const int* __restrict__ rows) {
    int i = blockIdx.x * blockDim.x + threadIdx.x;
    if (i < NNZ) atomicAdd(&g_cnt[rows[i]], 1);
}

__global__ void scan1_kernel() {                 // per-1024-block exclusive scan
    __shared__ int sh[1024];
    int i = blockIdx.x * 1024 + threadIdx.x;
    int v = (i < NTOT) ? g_cnt[i] : 0;
    sh[threadIdx.x] = v;
    __syncthreads();
    #pragma unroll
    for (int o = 1; o < 1024; o <<= 1) {
        int t = (threadIdx.x >= o) ? sh[threadIdx.x - o] : 0;
        __syncthreads();
        sh[threadIdx.x] += t;
        __syncthreads();
    }
    if (i < NTOT) g_row_ptr[i] = sh[threadIdx.x] - v;      // exclusive within block
    if (threadIdx.x == 1023) g_blocksum[blockIdx.x] = sh[1023];
}

__global__ void scan23_kernel() {                // blockoff reduce + apply + cursors
    __shared__ int sh[256];
    int i    = blockIdx.x * 256 + threadIdx.x;
    int sblk = (blockIdx.x * 256) >> 10;
    int t    = threadIdx.x;
    sh[t] = (t < NBLK && t < sblk) ? g_blocksum[t] : 0;
    __syncthreads();
    #pragma unroll
    for (int o = 128; o; o >>= 1) {
        if (t < o) sh[t] += sh[t + o];
        __syncthreads();
    }
    int off = sh[0];
    if (i >= NTOT) return;
    int v = g_row_ptr[i] + off;
    g_row_ptr[i] = v;
    g_cursor[i]  = v;
}

__global__ void scatter_kernel(const float* __restrict__ vals,
                               const int* __restrict__ rows,
                               const int* __restrict__ cols) {
    int i = blockIdx.x * blockDim.x + threadIdx.x;
    if (i >= NNZ) return;
    int r = rows[i];
    int pos = atomicAdd(&g_cursor[r], 1);
    g_pair[pos] = make_float2(vals[i], __int_as_float(cols[i]));
}

// ---------------------------------------------------------------------------
// Fused layer: gather-SpMM (CSR, half-warp per row, fp16 gather, fp32 accum)
//              + sign-noise perturb; last layer averages ego0+e1+e2+e3 -> out.
// ---------------------------------------------------------------------------
__device__ __forceinline__ float sgn(float x) {
    return (x > 0.f) ? 1.f : ((x < 0.f) ? -1.f : 0.f);
}

// L = 0: halfA -> halfB.  L = 1: halfB -> halfC.  L = 2: halfC -> averaged out.
template <int L>
__global__ void __launch_bounds__(256) layer_kernel(const float* __restrict__ noise_k,
                                                    const float* __restrict__ ue,
                                                    const float* __restrict__ ie,
                                                    float* __restrict__ out) {
    const __half* __restrict__ egoIn = (L == 0) ? g_halfA : ((L == 1) ? g_halfB : g_halfC);

    int hw = (blockIdx.x * blockDim.x + threadIdx.x) >> 4;  // half-warp = row
    int l  = threadIdx.x & 15;                              // 4-elem slice
    if (hw >= NTOT) return;

    int beg = g_row_ptr[hw];
    int end = g_row_ptr[hw + 1];

    float4 a = make_float4(0.f, 0.f, 0.f, 0.f);

    int j = beg;
    for (; j + 4 <= end; j += 4) {                          // unroll-4 for MLP
        float2 p0 = g_pair[j],     p1 = g_pair[j + 1];
        float2 p2 = g_pair[j + 2], p3 = g_pair[j + 3];
        float4 x0 = ldh4(egoIn + (long long)__float_as_int(p0.y) * EMB + 4 * l);
        float4 x1 = ldh4(egoIn + (long long)__float_as_int(p1.y) * EMB + 4 * l);
        float4 x2 = ldh4(egoIn + (long long)__float_as_int(p2.y) * EMB + 4 * l);
        float4 x3 = ldh4(egoIn + (long long)__float_as_int(p3.y) * EMB + 4 * l);
        a.x += p0.x * x0.x; a.y += p0.x * x0.y; a.z += p0.x * x0.z; a.w += p0.x * x0.w;
        a.x += p1.x * x1.x; a.y += p1.x * x1.y; a.z += p1.x * x1.z; a.w += p1.x * x1.w;
        a.x += p2.x * x2.x; a.y += p2.x * x2.y; a.z += p2.x * x2.z; a.w += p2.x * x2.w;
        a.x += p3.x * x3.x; a.y += p3.x * x3.y; a.z += p3.x * x3.z; a.w += p3.x * x3.w;
    }
    for (; j < end; ++j) {
        float2 p = g_pair[j];
        float4 x = ldh4(egoIn + (long long)__float_as_int(p.y) * EMB + 4 * l);
        a.x += p.x * x.x; a.y += p.x * x.y; a.z += p.x * x.z; a.w += p.x * x.w;
    }

    // noise row-norm over 64 elems (16 lanes x 4), shfl reduce within half-warp
    float4 n = ((const float4*)noise_k)[hw * 16 + l];
    float ss = n.x * n.x + n.y * n.y + n.z * n.z + n.w * n.w;
    ss += __shfl_xor_sync(0xffffffffu, ss, 8, 16);
    ss += __shfl_xor_sync(0xffffffffu, ss, 4, 16);
    ss += __shfl_xor_sync(0xffffffffu, ss, 2, 16);
    ss += __shfl_xor_sync(0xffffffffu, ss, 1, 16);
    float inv = EPS / fmaxf(sqrtf(ss), 1e-12f);

    float4 e;
    e.x = a.x + sgn(a.x) * n.x * inv;
    e.y = a.y + sgn(a.y) * n.y * inv;
    e.z = a.z + sgn(a.z) * n.z * inv;
    e.w = a.w + sgn(a.w) * n.w * inv;

    long long o = (long long)hw * EMB + 4 * l;              // element offset
    if (L == 0) {
        sth4(g_halfB + o, e);
    } else if (L == 1) {
        sth4(g_halfC + o, e);
    } else {
        // ego0 from the exact fp32 inputs; e1,e2 from the fp16 copies
        float4 z0;
        if (hw < USER_NUM) z0 = *(const float4*)(ue + o);
        else               z0 = *(const float4*)(ie + o - (long long)USER_NUM * EMB);
        float4 z1 = ldh4(g_halfB + o);
        float4 z2 = ldh4(g_halfC + o);
        *(float4*)(out + o) = make_float4((z0.x + z1.x + z2.x + e.x) * 0.25f,
                                          (z0.y + z1.y + z2.y + e.y) * 0.25f,
                                          (z0.z + z1.z + z2.z + e.z) * 0.25f,
                                          (z0.w + z1.w + z2.w + e.w) * 0.25f);
    }
}

// ---------------------------------------------------------------------------
// launch
// Inputs: 0 user_emb, 1 item_emb, 2 adj_vals, 3 noise, 4 adj_rows, 5 adj_cols
// ---------------------------------------------------------------------------
extern "C" void kernel_launch(void* const* d_in, const int* in_sizes, int n_in,
                              void* d_out, int out_size) {
    const float* ue    = (const float*)d_in[0];
    const float* ie    = (const float*)d_in[1];
    const float* vals  = (const float*)d_in[2];
    const float* noise = (const float*)d_in[3];
    const int*   rows  = (const int*)d_in[4];
    const int*   cols  = (const int*)d_in[5];
    float* out = (float*)d_out;
    (void)in_sizes; (void)n_in; (void)out_size;

    const int ew_blocks   = (NELEM / 4 + 255) / 256;
    const int nnz_blocks  = (NNZ + 255) / 256;
    const int row_blocks  = (NTOT + 255) / 256;
    const int lay_blocks  = (NTOT * 16 + 255) / 256;        // half-warp per row

    init_kernel<<<ew_blocks, 256>>>(ue, ie);

    // CSR build (reused by all 3 layers)
    hist_kernel<<<nnz_blocks, 256>>>(rows);
    scan1_kernel<<<NBLK, 1024>>>();
    scan23_kernel<<<row_blocks, 256>>>();
    scatter_kernel<<<nnz_blocks, 256>>>(vals, rows, cols);

    // 3 fused layers: halfA -> halfB -> halfC -> averaged out
    layer_kernel<0><<<lay_blocks, 256>>>(noise + 0LL * NELEM, ue, ie, out);
    layer_kernel<1><<<lay_blocks, 256>>>(noise + 1LL * NELEM, ue, ie, out);
    layer_kernel<2><<<lay_blocks, 256>>>(noise + 2LL * NELEM, ue, ie, out);
}